// round 15
// baseline (speedup 1.0000x reference)
#include <cuda_runtime.h>
#include <cuda_bf16.h>
#include <cuda_fp16.h>
#include <cstdint>
#include <cstddef>

// Problem constants
#define BB 2
#define TT 2048
#define DD 2048
#define HH 16
#define GG 4
#define DK 128
#define RF (HH / GG)   // 4

// ---------------------------------------------------------------------------
// Scratch (__device__ globals; no allocation allowed)
// ---------------------------------------------------------------------------
__device__ __align__(16) __half g_qh[(size_t)BB * TT * DD];        // roped q (pre-scaled)
__device__ __align__(16) __half g_kh[(size_t)BB * TT * 512];       // roped k
__device__ __align__(16) __half g_vh[(size_t)BB * TT * 512];       // v fp16
__device__ __align__(16) __half g_xh[(size_t)BB * TT * DD];        // x fp16
__device__ __align__(16) __half g_yh[(size_t)BB * TT * DD];        // attn out fp16
__device__ __align__(16) __half g_wt[(size_t)DD * 3072];           // [Wq|Wk|Wv] fp16, K-major
__device__ __align__(16) __half g_wo[(size_t)DD * DD];             // Wo fp16, K-major

// ---------------------------------------------------------------------------
// PTX helpers
// ---------------------------------------------------------------------------
__device__ __forceinline__ void cp16(uint32_t s, const void* g) {
    asm volatile("cp.async.cg.shared.global [%0], [%1], 16;"
                 :: "r"(s), "l"(__cvta_generic_to_global(g)));
}
#define CP_COMMIT() asm volatile("cp.async.commit_group;" ::: "memory")
#define CP_WAIT(n)  asm volatile("cp.async.wait_group %0;" :: "n"(n) : "memory")

__device__ __forceinline__ uint32_t smem_to_u32(const void* p) {
    uint32_t a;
    asm("{ .reg .u64 t; cvta.to.shared.u64 t, %1; cvt.u32.u64 %0, t; }"
        : "=r"(a) : "l"(p));
    return a;
}

__device__ __forceinline__ void mma16816(float* d, const uint32_t* a, const uint32_t* b) {
    asm volatile("mma.sync.aligned.m16n8k16.row.col.f32.f16.f16.f32 "
        "{%0,%1,%2,%3}, {%4,%5,%6,%7}, {%8,%9}, {%0,%1,%2,%3};"
        : "+f"(d[0]), "+f"(d[1]), "+f"(d[2]), "+f"(d[3])
        : "r"(a[0]), "r"(a[1]), "r"(a[2]), "r"(a[3]), "r"(b[0]), "r"(b[1]));
}
__device__ __forceinline__ void ldsm4(uint32_t* r, uint32_t addr) {
    asm volatile("ldmatrix.sync.aligned.m8n8.x4.shared.b16 {%0,%1,%2,%3}, [%4];"
        : "=r"(r[0]), "=r"(r[1]), "=r"(r[2]), "=r"(r[3]) : "r"(addr));
}
__device__ __forceinline__ void ldsm4t(uint32_t* r, uint32_t addr) {
    asm volatile("ldmatrix.sync.aligned.m8n8.x4.trans.shared.b16 {%0,%1,%2,%3}, [%4];"
        : "=r"(r[0]), "=r"(r[1]), "=r"(r[2]), "=r"(r[3]) : "r"(addr));
}
__device__ __forceinline__ uint32_t packh2(float a, float b) {
    __half2 h = __floats2half2_rn(a, b);
    return *(uint32_t*)&h;
}
__device__ __forceinline__ void store2(__half* p, float a, float b) {
    *(__half2*)p = __floats2half2_rn(a, b);
}
__device__ __forceinline__ void store2(float* p, float a, float b) {
    *(float2*)p = make_float2(a, b);
}

// ---------------------------------------------------------------------------
// Merged vectorized prep: x -> fp16; Wq|Wk|Wv -> wt; Wo -> wo (8 elems/thread)
// ---------------------------------------------------------------------------
#define N_X  ((size_t)BB * TT * DD)        // 8388608
#define N_W3 ((size_t)DD * 3072)           // 6291456
#define N_WO ((size_t)DD * DD)             // 4194304
#define N_ALL8 ((N_X + N_W3 + N_WO) / 8)   // 2359296

__device__ __forceinline__ void cvt8(const float* __restrict__ src, __half* __restrict__ dst) {
    float4 a = *(const float4*)src;
    float4 b = *(const float4*)(src + 4);
    uint4 o;
    o.x = packh2(a.x, a.y);
    o.y = packh2(a.z, a.w);
    o.z = packh2(b.x, b.y);
    o.w = packh2(b.z, b.w);
    *(uint4*)dst = o;
}

__global__ void prep_all(const float* __restrict__ x,
                         const float* __restrict__ Wq, const float* __restrict__ Wk,
                         const float* __restrict__ Wv, const float* __restrict__ Wo,
                         __half* __restrict__ xh, __half* __restrict__ wt,
                         __half* __restrict__ wo) {
    size_t tid8 = (size_t)blockIdx.x * blockDim.x + threadIdx.x;
    if (tid8 >= N_ALL8) return;
    size_t idx = tid8 * 8;
    if (idx < N_X) {
        cvt8(x + idx, xh + idx);
    } else if (idx < N_X + N_W3) {
        size_t i = idx - N_X;
        int k = (int)(i / 3072), c = (int)(i % 3072);
        const float* src;
        if (c < 2048)      src = Wq + (size_t)k * 2048 + c;
        else if (c < 2560) src = Wk + (size_t)k * 512 + (c - 2048);
        else               src = Wv + (size_t)k * 512 + (c - 2560);
        cvt8(src, wt + i);
    } else {
        size_t i = idx - N_X - N_W3;
        cvt8(Wo + i, wo + i);
    }
}

// ---------------------------------------------------------------------------
// Raw-mma fp16 GEMM (proven config): CTA 128x128x32, 256 threads = 8 warps
// (4m x 2n), 4-stage cp.async, 2 CTAs/SM.
// ROPE=true: fused RoPE epilogue writes qh/kh/vh. ROPE=false: fp32 store.
// ---------------------------------------------------------------------------
#define GBM 128
#define GBN 128
#define GBK 32
#define ALD 40
#define BLD 136
#define APLANE_B (128 * ALD * 2)          // 10240
#define BPLANE_B (32 * BLD * 2)           // 8704
#define STAGE_B (APLANE_B + BPLANE_B)     // 18944
#define NSTAGE 4
#define GEMM_SMEM (NSTAGE * STAGE_B)      // 75776
#define SP 136
#define RS_SCALE 0.08838834764831845f

template <bool ROPE>
__global__ __launch_bounds__(256, 2) void gemm_mma(const __half* __restrict__ A,
                                                   const __half* __restrict__ W,
                                                   float* __restrict__ C,
                                                   __half* __restrict__ qh,
                                                   __half* __restrict__ kh,
                                                   __half* __restrict__ vh,
                                                   int M, int N, int K) {
    extern __shared__ __align__(16) char smem[];
    const uint32_t sb = smem_to_u32(smem);
    const int tid  = threadIdx.x;
    const int lane = tid & 31;
    const int warp = tid >> 5;
    const int m0 = blockIdx.y * GBM;
    const int n0 = blockIdx.x * GBN;
    const int wm = (warp & 3) * 32;
    const int wn = (warp >> 2) * 64;

    const __half* Ap = A + (size_t)m0 * K;
    const __half* Wp = W + n0;

    auto load_stage = [&](int s, int kc) {
        uint32_t base = sb + (uint32_t)s * STAGE_B;
#pragma unroll
        for (int it = 0; it < 4; it++) {
            int id = it * 256 + tid;
            if (id < 512) {
                int row = id >> 2, c16 = (id & 3) * 16;
                cp16(base + (uint32_t)row * (ALD * 2) + c16,
                     Ap + (size_t)row * K + kc + (c16 >> 1));
            } else {
                int id2 = id - 512;
                int row = id2 >> 4, c16 = (id2 & 15) * 16;
                cp16(base + APLANE_B + (uint32_t)row * (BLD * 2) + c16,
                     Wp + (size_t)(kc + row) * N + (c16 >> 1));
            }
        }
        CP_COMMIT();
    };

    const int mm   = lane >> 3;
    const int arow = (mm & 1) * 8 + (lane & 7);
    const int acol = (mm >> 1) * 8;

    float acc[2][8][4];
#pragma unroll
    for (int i = 0; i < 2; i++)
#pragma unroll
        for (int j = 0; j < 8; j++)
#pragma unroll
            for (int r = 0; r < 4; r++) acc[i][j][r] = 0.f;

    const int nch = K / GBK;
    load_stage(0, 0);
    load_stage(1, GBK);
    load_stage(2, 2 * GBK);

    for (int ch = 0; ch < nch; ch++) {
        const int s = ch & 3;
        if (ch + 3 < nch) {
            load_stage((ch + 3) & 3, (ch + 3) * GBK);
            CP_WAIT(3);
        } else if (ch + 2 < nch) {
            CP_WAIT(2);
        } else if (ch + 1 < nch) {
            CP_WAIT(1);
        } else {
            CP_WAIT(0);
        }
        __syncthreads();

        const uint32_t As = sb + (uint32_t)s * STAGE_B;
        const uint32_t Bs = As + APLANE_B;

#pragma unroll
        for (int ks = 0; ks < GBK; ks += 16) {
            uint32_t af[2][4];
            ldsm4(af[0], As + ((wm + arow) * ALD + ks + acol) * 2);
            ldsm4(af[1], As + ((wm + 16 + arow) * ALD + ks + acol) * 2);
            uint32_t bf[4][4];
#pragma unroll
            for (int j = 0; j < 4; j++)
                ldsm4t(bf[j], Bs + ((ks + arow) * BLD + wn + j * 16 + acol) * 2);
#pragma unroll
            for (int i = 0; i < 2; i++)
#pragma unroll
                for (int j = 0; j < 4; j++) {
                    mma16816(acc[i][2 * j],     af[i], bf[j]);
                    mma16816(acc[i][2 * j + 1], af[i], bf[j] + 2);
                }
        }
        __syncthreads();
    }

    const int r0 = lane >> 2;
    const int c0 = (lane & 3) * 2;

    if (!ROPE) {
#pragma unroll
        for (int i = 0; i < 2; i++) {
            size_t rowa = (size_t)(m0 + wm + i * 16 + r0) * N + n0 + wn + c0;
            size_t rowb = rowa + (size_t)8 * N;
#pragma unroll
            for (int j = 0; j < 8; j++) {
                store2(C + rowa + j * 8, acc[i][j][0], acc[i][j][1]);
                store2(C + rowb + j * 8, acc[i][j][2], acc[i][j][3]);
            }
        }
        return;
    }

    // ---- Fused RoPE epilogue ----
    __half* st = (__half*)smem;
#pragma unroll
    for (int i = 0; i < 2; i++) {
        __half* ra = st + (wm + i * 16 + r0) * SP + wn + c0;
        __half* rb = ra + 8 * SP;
#pragma unroll
        for (int j = 0; j < 8; j++) {
            store2(ra + j * 8, acc[i][j][0], acc[i][j][1]);
            store2(rb + j * 8, acc[i][j][2], acc[i][j][3]);
        }
    }
    __syncthreads();

    int region, head;
    if (n0 < 2048)      { region = 0; head = n0 >> 7; }
    else if (n0 < 2560) { region = 1; head = (n0 - 2048) >> 7; }
    else                { region = 2; head = (n0 - 2560) >> 7; }

    const float log_theta_over_64 = 0.14391156f;

    for (int rr = warp; rr < 128; rr += 8) {
        const int gm = m0 + rr;
        const int t  = gm & (TT - 1);
        if (region == 2) {
            __half* dst = vh + (size_t)gm * 512 + head * 128;
            *(uint2*)(dst + lane * 4) = *(const uint2*)(st + rr * SP + lane * 4);
        } else {
            const float scale = (region == 0) ? RS_SCALE : 1.f;
            __half* dst = (region == 0) ? (qh + (size_t)gm * DD + head * 128)
                                        : (kh + (size_t)gm * 512 + head * 128);
            // lane handles rotation pairs p = 2*lane, 2*lane+1
            int p = lane * 2;
            float f0 = __expf(-(float)p * log_theta_over_64);
            float f1 = __expf(-(float)(p + 1) * log_theta_over_64);
            float s0, c0r, s1, c1r;
            sincosf((float)t * f0, &s0, &c0r);
            sincosf((float)t * f1, &s1, &c1r);
            float x10 = __half2float(st[rr * SP + p]);
            float x11 = __half2float(st[rr * SP + p + 1]);
            float x20 = __half2float(st[rr * SP + p + 64]);
            float x21 = __half2float(st[rr * SP + p + 65]);
            store2(dst + p,      (x10 * c0r - x20 * s0) * scale, (x11 * c1r - x21 * s1) * scale);
            store2(dst + p + 64, (x20 * c0r + x10 * s0) * scale, (x21 * c1r + x11 * s1) * scale);
        }
    }
}

// ---------------------------------------------------------------------------
// Flash attention: BQ=64, BK=64, 128 threads = 4 warps (16 q-rows each),
// double-buffered K/V (69.6KB smem), 3 CTAs/SM (12 warps) — independent
// barrier domains hide CP_WAIT/sync/softmax bubbles.
// ---------------------------------------------------------------------------
#define KP 136
#define ATILE_H (64 * KP)
#define ATT_SMEM (4 * ATILE_H * 2)        // 69632

__global__ __launch_bounds__(128, 3) void attn_h(const __half* __restrict__ q,
                                                 const __half* __restrict__ k,
                                                 const __half* __restrict__ v,
                                                 __half* __restrict__ yh) {
    extern __shared__ __align__(16) __half asm_[];
    __half* KsA[2] = {asm_, asm_ + ATILE_H};
    __half* VsA[2] = {asm_ + 2 * ATILE_H, asm_ + 3 * ATILE_H};

    const int qt = (int)gridDim.x - 1 - (int)blockIdx.x;  // longest first
    const int h  = blockIdx.y;
    const int b  = blockIdx.z;
    const int q0 = qt * 64;
    const int g  = h / RF;

    const int tid  = threadIdx.x;
    const int lane = tid & 31;
    const int warp = tid >> 5;
    const int wrow = warp * 16;

    // Stage Q into KsA[0]
    for (int i = tid; i < 64 * 16; i += 128) {
        int row = i >> 4, c8 = (i & 15) * 8;
        *(uint4*)(KsA[0] + row * KP + c8) =
            *(const uint4*)(q + ((size_t)(b * TT + q0 + row)) * DD + h * DK + c8);
    }
    __syncthreads();

    const int mm   = lane >> 3;
    const int arow = (mm & 1) * 8 + (lane & 7);
    const int acol = (mm >> 1) * 8;
    const int brow = (mm >> 1) * 8 + (lane & 7);
    const int bcol = (mm & 1) * 8;

    uint32_t Qa[8][4];
#pragma unroll
    for (int kc = 0; kc < 8; kc++)
        ldsm4(Qa[kc], smem_to_u32(KsA[0] + (wrow + arow) * KP + kc * 16 + acol));
    __syncthreads();

    auto load_kv = [&](int kt, int s) {
        uint32_t kb = smem_to_u32(KsA[s]);
        uint32_t vb = smem_to_u32(VsA[s]);
        const __half* kp = k + ((size_t)(b * TT + kt * 64)) * 512 + g * DK;
        const __half* vp = v + ((size_t)(b * TT + kt * 64)) * 512 + g * DK;
        for (int i = tid; i < 1024; i += 128) {
            int row = i >> 4, cb = (i & 15) * 16;
            uint32_t so = (uint32_t)(row * (KP * 2) + cb);
            cp16(kb + so, (const char*)(kp + (size_t)row * 512) + cb);
            cp16(vb + so, (const char*)(vp + (size_t)row * 512) + cb);
        }
        CP_COMMIT();
    };

    float Ofr[16][4];
#pragma unroll
    for (int nb = 0; nb < 16; nb++)
#pragma unroll
        for (int j = 0; j < 4; j++) Ofr[nb][j] = 0.f;

    float m0r = -1e30f, m1r = -1e30f, l0r = 0.f, l1r = 0.f;
    const int r0 = lane >> 2;
    const int c0 = (lane & 3) * 2;

    load_kv(0, 0);

    for (int kt = 0; kt <= qt; kt++) {
        const int s = kt & 1;
        if (kt < qt) {
            load_kv(kt + 1, s ^ 1);
            CP_WAIT(1);
        } else {
            CP_WAIT(0);
        }
        __syncthreads();
        const __half* Ks = KsA[s];
        const __half* Vs = VsA[s];

        float S[8][4];
#pragma unroll
        for (int nb = 0; nb < 8; nb++)
#pragma unroll
            for (int j = 0; j < 4; j++) S[nb][j] = 0.f;

#pragma unroll
        for (int kc = 0; kc < 8; kc++)
#pragma unroll
            for (int nbp = 0; nbp < 4; nbp++) {
                uint32_t bb[4];
                ldsm4(bb, smem_to_u32(Ks + (nbp * 16 + brow) * KP + kc * 16 + bcol));
                mma16816(S[2 * nbp],     Qa[kc], bb);
                mma16816(S[2 * nbp + 1], Qa[kc], bb + 2);
            }

        if (kt == qt) {
            const int rl0 = wrow + r0, rl1 = rl0 + 8;
#pragma unroll
            for (int nb = 0; nb < 8; nb++) {
                int colb = nb * 8 + c0;
                if (colb     > rl0) S[nb][0] = -1e30f;
                if (colb + 1 > rl0) S[nb][1] = -1e30f;
                if (colb     > rl1) S[nb][2] = -1e30f;
                if (colb + 1 > rl1) S[nb][3] = -1e30f;
            }
        }

        float mx0 = -1e30f, mx1 = -1e30f;
#pragma unroll
        for (int nb = 0; nb < 8; nb++) {
            mx0 = fmaxf(mx0, fmaxf(S[nb][0], S[nb][1]));
            mx1 = fmaxf(mx1, fmaxf(S[nb][2], S[nb][3]));
        }
        mx0 = fmaxf(mx0, __shfl_xor_sync(0xffffffffu, mx0, 1));
        mx0 = fmaxf(mx0, __shfl_xor_sync(0xffffffffu, mx0, 2));
        mx1 = fmaxf(mx1, __shfl_xor_sync(0xffffffffu, mx1, 1));
        mx1 = fmaxf(mx1, __shfl_xor_sync(0xffffffffu, mx1, 2));

        float mn0 = fmaxf(m0r, mx0), mn1 = fmaxf(m1r, mx1);
        float a0 = __expf(m0r - mn0), a1 = __expf(m1r - mn1);
        float s0 = 0.f, s1 = 0.f;
#pragma unroll
        for (int nb = 0; nb < 8; nb++) {
            S[nb][0] = __expf(S[nb][0] - mn0);
            S[nb][1] = __expf(S[nb][1] - mn0);
            S[nb][2] = __expf(S[nb][2] - mn1);
            S[nb][3] = __expf(S[nb][3] - mn1);
            s0 += S[nb][0] + S[nb][1];
            s1 += S[nb][2] + S[nb][3];
        }
        s0 += __shfl_xor_sync(0xffffffffu, s0, 1);
        s0 += __shfl_xor_sync(0xffffffffu, s0, 2);
        s1 += __shfl_xor_sync(0xffffffffu, s1, 1);
        s1 += __shfl_xor_sync(0xffffffffu, s1, 2);
        l0r = l0r * a0 + s0;
        l1r = l1r * a1 + s1;
        m0r = mn0; m1r = mn1;

#pragma unroll
        for (int nb = 0; nb < 16; nb++) {
            Ofr[nb][0] *= a0; Ofr[nb][1] *= a0;
            Ofr[nb][2] *= a1; Ofr[nb][3] *= a1;
        }

        uint32_t Pa[4][4];
#pragma unroll
        for (int kc = 0; kc < 4; kc++) {
            Pa[kc][0] = packh2(S[2 * kc][0],     S[2 * kc][1]);
            Pa[kc][1] = packh2(S[2 * kc][2],     S[2 * kc][3]);
            Pa[kc][2] = packh2(S[2 * kc + 1][0], S[2 * kc + 1][1]);
            Pa[kc][3] = packh2(S[2 * kc + 1][2], S[2 * kc + 1][3]);
        }

#pragma unroll
        for (int kc = 0; kc < 4; kc++)
#pragma unroll
            for (int nbp = 0; nbp < 8; nbp++) {
                uint32_t bb[4];
                ldsm4t(bb, smem_to_u32(Vs + (kc * 16 + arow) * KP + nbp * 16 + acol));
                mma16816(Ofr[2 * nbp],     Pa[kc], bb);
                mma16816(Ofr[2 * nbp + 1], Pa[kc], bb + 2);
            }
        __syncthreads();
    }

    // Epilogue: normalize, write fp16 y.
    const float i0 = 1.f / l0r, i1 = 1.f / l1r;
#pragma unroll
    for (int nb = 0; nb < 16; nb++) {
        size_t base0 = ((size_t)(b * TT + q0 + wrow + r0)) * DD + h * DK + nb * 8 + c0;
        size_t base1 = base0 + (size_t)8 * DD;
        *(__half2*)(yh + base0) = __floats2half2_rn(Ofr[nb][0] * i0, Ofr[nb][1] * i0);
        *(__half2*)(yh + base1) = __floats2half2_rn(Ofr[nb][2] * i1, Ofr[nb][3] * i1);
    }
}

// ---------------------------------------------------------------------------
// Launch
// ---------------------------------------------------------------------------
extern "C" void kernel_launch(void* const* d_in, const int* in_sizes, int n_in,
                              void* d_out, int out_size) {
    const float* x  = (const float*)d_in[0];
    const float* Wq = (const float*)d_in[1];
    const float* Wk = (const float*)d_in[2];
    const float* Wv = (const float*)d_in[3];
    const float* Wo = (const float*)d_in[4];
    float* out = (float*)d_out;

    __half *qh, *kh, *vh, *xh, *yh, *wt, *wo;
    cudaGetSymbolAddress((void**)&qh, g_qh);
    cudaGetSymbolAddress((void**)&kh, g_kh);
    cudaGetSymbolAddress((void**)&vh, g_vh);
    cudaGetSymbolAddress((void**)&xh, g_xh);
    cudaGetSymbolAddress((void**)&yh, g_yh);
    cudaGetSymbolAddress((void**)&wt, g_wt);
    cudaGetSymbolAddress((void**)&wo, g_wo);

    const int M = BB * TT;            // 4096

    // Single vectorized prep launch
    prep_all<<<(int)((N_ALL8 + 255) / 256), 256>>>(x, Wq, Wk, Wv, Wo, xh, wt, wo);

    cudaFuncSetAttribute(gemm_mma<true>,  cudaFuncAttributeMaxDynamicSharedMemorySize, GEMM_SMEM);
    cudaFuncSetAttribute(gemm_mma<false>, cudaFuncAttributeMaxDynamicSharedMemorySize, GEMM_SMEM);

    // Fused QKV projection + RoPE epilogue
    gemm_mma<true><<<dim3(3072 / GBN, M / GBM), 256, GEMM_SMEM>>>(
        xh, wt, nullptr, qh, kh, vh, M, 3072, DD);

    // Attention (BQ=64, 128 threads, 3 CTAs/SM)
    cudaFuncSetAttribute(attn_h, cudaFuncAttributeMaxDynamicSharedMemorySize, ATT_SMEM);
    attn_h<<<dim3(TT / 64, HH, BB), 128, ATT_SMEM>>>(qh, kh, vh, yh);

    // Output projection (fp32 out)
    gemm_mma<false><<<dim3(DD / GBN, M / GBM), 256, GEMM_SMEM>>>(
        yh, wo, out, nullptr, nullptr, nullptr, M, DD, DD);
}

// round 16
// speedup vs baseline: 1.0458x; 1.0458x over previous
#include <cuda_runtime.h>
#include <cuda_bf16.h>
#include <cuda_fp16.h>
#include <cstdint>
#include <cstddef>

// Problem constants
#define BB 2
#define TT 2048
#define DD 2048
#define HH 16
#define GG 4
#define DK 128
#define RF (HH / GG)   // 4

// ---------------------------------------------------------------------------
// Scratch (__device__ globals; no allocation allowed)
// ---------------------------------------------------------------------------
__device__ __align__(16) __half g_qh[(size_t)BB * TT * DD];        // roped q (scaled by rs*log2e)
__device__ __align__(16) __half g_kh[(size_t)BB * TT * 512];       // roped k
__device__ __align__(16) __half g_vh[(size_t)BB * TT * 512];       // v fp16
__device__ __align__(16) __half g_xh[(size_t)BB * TT * DD];        // x fp16
__device__ __align__(16) __half g_yh[(size_t)BB * TT * DD];        // attn out fp16
__device__ __align__(16) __half g_wt[(size_t)DD * 3072];           // [Wq|Wk|Wv] fp16, K-major
__device__ __align__(16) __half g_wo[(size_t)DD * DD];             // Wo fp16, K-major

// ---------------------------------------------------------------------------
// PTX helpers
// ---------------------------------------------------------------------------
__device__ __forceinline__ void cp16(uint32_t s, const void* g) {
    asm volatile("cp.async.cg.shared.global [%0], [%1], 16;"
                 :: "r"(s), "l"(__cvta_generic_to_global(g)));
}
#define CP_COMMIT() asm volatile("cp.async.commit_group;" ::: "memory")
#define CP_WAIT(n)  asm volatile("cp.async.wait_group %0;" :: "n"(n) : "memory")

__device__ __forceinline__ uint32_t smem_to_u32(const void* p) {
    uint32_t a;
    asm("{ .reg .u64 t; cvta.to.shared.u64 t, %1; cvt.u32.u64 %0, t; }"
        : "=r"(a) : "l"(p));
    return a;
}

__device__ __forceinline__ void mma16816(float* d, const uint32_t* a, const uint32_t* b) {
    asm volatile("mma.sync.aligned.m16n8k16.row.col.f32.f16.f16.f32 "
        "{%0,%1,%2,%3}, {%4,%5,%6,%7}, {%8,%9}, {%0,%1,%2,%3};"
        : "+f"(d[0]), "+f"(d[1]), "+f"(d[2]), "+f"(d[3])
        : "r"(a[0]), "r"(a[1]), "r"(a[2]), "r"(a[3]), "r"(b[0]), "r"(b[1]));
}
__device__ __forceinline__ void ldsm4(uint32_t* r, uint32_t addr) {
    asm volatile("ldmatrix.sync.aligned.m8n8.x4.shared.b16 {%0,%1,%2,%3}, [%4];"
        : "=r"(r[0]), "=r"(r[1]), "=r"(r[2]), "=r"(r[3]) : "r"(addr));
}
__device__ __forceinline__ void ldsm4t(uint32_t* r, uint32_t addr) {
    asm volatile("ldmatrix.sync.aligned.m8n8.x4.trans.shared.b16 {%0,%1,%2,%3}, [%4];"
        : "=r"(r[0]), "=r"(r[1]), "=r"(r[2]), "=r"(r[3]) : "r"(addr));
}
__device__ __forceinline__ uint32_t packh2(float a, float b) {
    __half2 h = __floats2half2_rn(a, b);
    return *(uint32_t*)&h;
}
__device__ __forceinline__ void store2(__half* p, float a, float b) {
    *(__half2*)p = __floats2half2_rn(a, b);
}
__device__ __forceinline__ void store2(float* p, float a, float b) {
    *(float2*)p = make_float2(a, b);
}
// bare MUFU exp2 (softmax runs in log2 domain; q pre-scaled by rs*log2e)
__device__ __forceinline__ float ex2f(float x) {
    float r;
    asm("ex2.approx.f32 %0, %1;" : "=f"(r) : "f"(x));
    return r;
}

// ---------------------------------------------------------------------------
// Merged vectorized prep: x -> fp16; Wq|Wk|Wv -> wt; Wo -> wo (8 elems/thread)
// ---------------------------------------------------------------------------
#define N_X  ((size_t)BB * TT * DD)
#define N_W3 ((size_t)DD * 3072)
#define N_WO ((size_t)DD * DD)
#define N_ALL8 ((N_X + N_W3 + N_WO) / 8)

__device__ __forceinline__ void cvt8(const float* __restrict__ src, __half* __restrict__ dst) {
    float4 a = *(const float4*)src;
    float4 b = *(const float4*)(src + 4);
    uint4 o;
    o.x = packh2(a.x, a.y);
    o.y = packh2(a.z, a.w);
    o.z = packh2(b.x, b.y);
    o.w = packh2(b.z, b.w);
    *(uint4*)dst = o;
}

__global__ void prep_all(const float* __restrict__ x,
                         const float* __restrict__ Wq, const float* __restrict__ Wk,
                         const float* __restrict__ Wv, const float* __restrict__ Wo,
                         __half* __restrict__ xh, __half* __restrict__ wt,
                         __half* __restrict__ wo) {
    size_t tid8 = (size_t)blockIdx.x * blockDim.x + threadIdx.x;
    if (tid8 >= N_ALL8) return;
    size_t idx = tid8 * 8;
    if (idx < N_X) {
        cvt8(x + idx, xh + idx);
    } else if (idx < N_X + N_W3) {
        size_t i = idx - N_X;
        int k = (int)(i / 3072), c = (int)(i % 3072);
        const float* src;
        if (c < 2048)      src = Wq + (size_t)k * 2048 + c;
        else if (c < 2560) src = Wk + (size_t)k * 512 + (c - 2048);
        else               src = Wv + (size_t)k * 512 + (c - 2560);
        cvt8(src, wt + i);
    } else {
        size_t i = idx - N_X - N_W3;
        cvt8(Wo + i, wo + i);
    }
}

// ---------------------------------------------------------------------------
// Raw-mma fp16 GEMM (proven config): CTA 128x128x32, 256 threads = 8 warps
// (4m x 2n), 4-stage cp.async, 2 CTAs/SM.
// ROPE=true: fused RoPE epilogue writes qh/kh/vh (q scaled by rs*log2e).
// ---------------------------------------------------------------------------
#define GBM 128
#define GBN 128
#define GBK 32
#define ALD 40
#define BLD 136
#define APLANE_B (128 * ALD * 2)
#define BPLANE_B (32 * BLD * 2)
#define STAGE_B (APLANE_B + BPLANE_B)
#define NSTAGE 4
#define GEMM_SMEM (NSTAGE * STAGE_B)
#define SP 136
// 1/sqrt(128) * log2(e): softmax computed with exp2
#define QSCALE (0.08838834764831845f * 1.4426950408889634f)

template <bool ROPE>
__global__ __launch_bounds__(256, 2) void gemm_mma(const __half* __restrict__ A,
                                                   const __half* __restrict__ W,
                                                   float* __restrict__ C,
                                                   __half* __restrict__ qh,
                                                   __half* __restrict__ kh,
                                                   __half* __restrict__ vh,
                                                   int M, int N, int K) {
    extern __shared__ __align__(16) char smem[];
    const uint32_t sb = smem_to_u32(smem);
    const int tid  = threadIdx.x;
    const int lane = tid & 31;
    const int warp = tid >> 5;
    const int m0 = blockIdx.y * GBM;
    const int n0 = blockIdx.x * GBN;
    const int wm = (warp & 3) * 32;
    const int wn = (warp >> 2) * 64;

    const __half* Ap = A + (size_t)m0 * K;
    const __half* Wp = W + n0;

    auto load_stage = [&](int s, int kc) {
        uint32_t base = sb + (uint32_t)s * STAGE_B;
#pragma unroll
        for (int it = 0; it < 4; it++) {
            int id = it * 256 + tid;
            if (id < 512) {
                int row = id >> 2, c16 = (id & 3) * 16;
                cp16(base + (uint32_t)row * (ALD * 2) + c16,
                     Ap + (size_t)row * K + kc + (c16 >> 1));
            } else {
                int id2 = id - 512;
                int row = id2 >> 4, c16 = (id2 & 15) * 16;
                cp16(base + APLANE_B + (uint32_t)row * (BLD * 2) + c16,
                     Wp + (size_t)(kc + row) * N + (c16 >> 1));
            }
        }
        CP_COMMIT();
    };

    const int mm   = lane >> 3;
    const int arow = (mm & 1) * 8 + (lane & 7);
    const int acol = (mm >> 1) * 8;

    float acc[2][8][4];
#pragma unroll
    for (int i = 0; i < 2; i++)
#pragma unroll
        for (int j = 0; j < 8; j++)
#pragma unroll
            for (int r = 0; r < 4; r++) acc[i][j][r] = 0.f;

    const int nch = K / GBK;
    load_stage(0, 0);
    load_stage(1, GBK);
    load_stage(2, 2 * GBK);

    for (int ch = 0; ch < nch; ch++) {
        const int s = ch & 3;
        if (ch + 3 < nch) {
            load_stage((ch + 3) & 3, (ch + 3) * GBK);
            CP_WAIT(3);
        } else if (ch + 2 < nch) {
            CP_WAIT(2);
        } else if (ch + 1 < nch) {
            CP_WAIT(1);
        } else {
            CP_WAIT(0);
        }
        __syncthreads();

        const uint32_t As = sb + (uint32_t)s * STAGE_B;
        const uint32_t Bs = As + APLANE_B;

#pragma unroll
        for (int ks = 0; ks < GBK; ks += 16) {
            uint32_t af[2][4];
            ldsm4(af[0], As + ((wm + arow) * ALD + ks + acol) * 2);
            ldsm4(af[1], As + ((wm + 16 + arow) * ALD + ks + acol) * 2);
            uint32_t bf[4][4];
#pragma unroll
            for (int j = 0; j < 4; j++)
                ldsm4t(bf[j], Bs + ((ks + arow) * BLD + wn + j * 16 + acol) * 2);
#pragma unroll
            for (int i = 0; i < 2; i++)
#pragma unroll
                for (int j = 0; j < 4; j++) {
                    mma16816(acc[i][2 * j],     af[i], bf[j]);
                    mma16816(acc[i][2 * j + 1], af[i], bf[j] + 2);
                }
        }
        __syncthreads();
    }

    const int r0 = lane >> 2;
    const int c0 = (lane & 3) * 2;

    if (!ROPE) {
#pragma unroll
        for (int i = 0; i < 2; i++) {
            size_t rowa = (size_t)(m0 + wm + i * 16 + r0) * N + n0 + wn + c0;
            size_t rowb = rowa + (size_t)8 * N;
#pragma unroll
            for (int j = 0; j < 8; j++) {
                store2(C + rowa + j * 8, acc[i][j][0], acc[i][j][1]);
                store2(C + rowb + j * 8, acc[i][j][2], acc[i][j][3]);
            }
        }
        return;
    }

    // ---- Fused RoPE epilogue ----
    __half* st = (__half*)smem;
#pragma unroll
    for (int i = 0; i < 2; i++) {
        __half* ra = st + (wm + i * 16 + r0) * SP + wn + c0;
        __half* rb = ra + 8 * SP;
#pragma unroll
        for (int j = 0; j < 8; j++) {
            store2(ra + j * 8, acc[i][j][0], acc[i][j][1]);
            store2(rb + j * 8, acc[i][j][2], acc[i][j][3]);
        }
    }
    __syncthreads();

    int region, head;
    if (n0 < 2048)      { region = 0; head = n0 >> 7; }
    else if (n0 < 2560) { region = 1; head = (n0 - 2048) >> 7; }
    else                { region = 2; head = (n0 - 2560) >> 7; }

    const float log_theta_over_64 = 0.14391156f;

    for (int rr = warp; rr < 128; rr += 8) {
        const int gm = m0 + rr;
        const int t  = gm & (TT - 1);
        if (region == 2) {
            __half* dst = vh + (size_t)gm * 512 + head * 128;
            *(uint2*)(dst + lane * 4) = *(const uint2*)(st + rr * SP + lane * 4);
        } else {
            const float scale = (region == 0) ? QSCALE : 1.f;
            __half* dst = (region == 0) ? (qh + (size_t)gm * DD + head * 128)
                                        : (kh + (size_t)gm * 512 + head * 128);
            int p = lane * 2;
            float f0 = __expf(-(float)p * log_theta_over_64);
            float f1 = __expf(-(float)(p + 1) * log_theta_over_64);
            float s0, c0r, s1, c1r;
            sincosf((float)t * f0, &s0, &c0r);
            sincosf((float)t * f1, &s1, &c1r);
            float x10 = __half2float(st[rr * SP + p]);
            float x11 = __half2float(st[rr * SP + p + 1]);
            float x20 = __half2float(st[rr * SP + p + 64]);
            float x21 = __half2float(st[rr * SP + p + 65]);
            store2(dst + p,      (x10 * c0r - x20 * s0) * scale, (x11 * c1r - x21 * s1) * scale);
            store2(dst + p + 64, (x20 * c0r + x10 * s0) * scale, (x21 * c1r + x11 * s1) * scale);
        }
    }
}

// ---------------------------------------------------------------------------
// Flash attention: BQ=64, BK=64, 128 threads = 4 warps (16 q-rows each).
// 3-stage K/V ring, ONE __syncthreads per tile, 2 CTAs/SM.
// Softmax in log2 domain (q pre-scaled by rs*log2e), bare ex2 MUFU.
// ---------------------------------------------------------------------------
#define KP 136
#define ATILE_H (64 * KP)                 // halves per K (or V) tile
#define ASTG_H (2 * ATILE_H)              // halves per stage (K+V)
#define ATT_SMEM (3 * ASTG_H * 2)         // 104448 bytes

__global__ __launch_bounds__(128, 2) void attn_h(const __half* __restrict__ q,
                                                 const __half* __restrict__ k,
                                                 const __half* __restrict__ v,
                                                 __half* __restrict__ yh) {
    extern __shared__ __align__(16) __half asm_[];

    const int qt = (int)gridDim.x - 1 - (int)blockIdx.x;  // longest first
    const int h  = blockIdx.y;
    const int b  = blockIdx.z;
    const int q0 = qt * 64;
    const int g  = h / RF;

    const int tid  = threadIdx.x;
    const int lane = tid & 31;
    const int warp = tid >> 5;
    const int wrow = warp * 16;

    // Stage Q into stage-0 K region (same footprint)
    for (int i = tid; i < 64 * 16; i += 128) {
        int row = i >> 4, c8 = (i & 15) * 8;
        *(uint4*)(asm_ + row * KP + c8) =
            *(const uint4*)(q + ((size_t)(b * TT + q0 + row)) * DD + h * DK + c8);
    }
    __syncthreads();

    const int mm   = lane >> 3;
    const int arow = (mm & 1) * 8 + (lane & 7);
    const int acol = (mm >> 1) * 8;
    const int brow = (mm >> 1) * 8 + (lane & 7);
    const int bcol = (mm & 1) * 8;

    uint32_t Qa[8][4];
#pragma unroll
    for (int kc = 0; kc < 8; kc++)
        ldsm4(Qa[kc], smem_to_u32(asm_ + (wrow + arow) * KP + kc * 16 + acol));
    __syncthreads();

    auto load_kv = [&](int kt, int s) {
        uint32_t kb = smem_to_u32(asm_ + s * ASTG_H);
        uint32_t vb = kb + ATILE_H * 2;
        const __half* kp = k + ((size_t)(b * TT + kt * 64)) * 512 + g * DK;
        const __half* vp = v + ((size_t)(b * TT + kt * 64)) * 512 + g * DK;
        for (int i = tid; i < 1024; i += 128) {
            int row = i >> 4, cb = (i & 15) * 16;
            uint32_t so = (uint32_t)(row * (KP * 2) + cb);
            cp16(kb + so, (const char*)(kp + (size_t)row * 512) + cb);
            cp16(vb + so, (const char*)(vp + (size_t)row * 512) + cb);
        }
        CP_COMMIT();
    };

    float Ofr[16][4];
#pragma unroll
    for (int nb = 0; nb < 16; nb++)
#pragma unroll
        for (int j = 0; j < 4; j++) Ofr[nb][j] = 0.f;

    float m0r = -1e30f, m1r = -1e30f, l0r = 0.f, l1r = 0.f;
    const int r0 = lane >> 2;
    const int c0 = (lane & 3) * 2;

    const int nkt = qt + 1;
    load_kv(0, 0);
    if (nkt > 1) load_kv(1, 1);

    for (int kt = 0; kt < nkt; kt++) {
        const int s = kt % 3;
        if (kt + 1 < nkt) CP_WAIT(1); else CP_WAIT(0);
        __syncthreads();                                    // kt data visible; kt-1 done by all
        if (kt + 2 < nkt) load_kv(kt + 2, (kt + 2) % 3);    // targets stage (kt-1)%3 — safe

        const __half* Ks = asm_ + s * ASTG_H;
        const __half* Vs = Ks + ATILE_H;

        float S[8][4];
#pragma unroll
        for (int nb = 0; nb < 8; nb++)
#pragma unroll
            for (int j = 0; j < 4; j++) S[nb][j] = 0.f;

#pragma unroll
        for (int kc = 0; kc < 8; kc++)
#pragma unroll
            for (int nbp = 0; nbp < 4; nbp++) {
                uint32_t bb[4];
                ldsm4(bb, smem_to_u32(Ks + (nbp * 16 + brow) * KP + kc * 16 + bcol));
                mma16816(S[2 * nbp],     Qa[kc], bb);
                mma16816(S[2 * nbp + 1], Qa[kc], bb + 2);
            }

        if (kt == qt) {                 // diagonal tile
            const int rl0 = wrow + r0, rl1 = rl0 + 8;
#pragma unroll
            for (int nb = 0; nb < 8; nb++) {
                int colb = nb * 8 + c0;
                if (colb     > rl0) S[nb][0] = -1e30f;
                if (colb + 1 > rl0) S[nb][1] = -1e30f;
                if (colb     > rl1) S[nb][2] = -1e30f;
                if (colb + 1 > rl1) S[nb][3] = -1e30f;
            }
        }

        float mx0 = -1e30f, mx1 = -1e30f;
#pragma unroll
        for (int nb = 0; nb < 8; nb++) {
            mx0 = fmaxf(mx0, fmaxf(S[nb][0], S[nb][1]));
            mx1 = fmaxf(mx1, fmaxf(S[nb][2], S[nb][3]));
        }
        mx0 = fmaxf(mx0, __shfl_xor_sync(0xffffffffu, mx0, 1));
        mx0 = fmaxf(mx0, __shfl_xor_sync(0xffffffffu, mx0, 2));
        mx1 = fmaxf(mx1, __shfl_xor_sync(0xffffffffu, mx1, 1));
        mx1 = fmaxf(mx1, __shfl_xor_sync(0xffffffffu, mx1, 2));

        float mn0 = fmaxf(m0r, mx0), mn1 = fmaxf(m1r, mx1);
        float a0 = ex2f(m0r - mn0), a1 = ex2f(m1r - mn1);
        float s0 = 0.f, s1 = 0.f;
#pragma unroll
        for (int nb = 0; nb < 8; nb++) {
            S[nb][0] = ex2f(S[nb][0] - mn0);
            S[nb][1] = ex2f(S[nb][1] - mn0);
            S[nb][2] = ex2f(S[nb][2] - mn1);
            S[nb][3] = ex2f(S[nb][3] - mn1);
            s0 += S[nb][0] + S[nb][1];
            s1 += S[nb][2] + S[nb][3];
        }
        s0 += __shfl_xor_sync(0xffffffffu, s0, 1);
        s0 += __shfl_xor_sync(0xffffffffu, s0, 2);
        s1 += __shfl_xor_sync(0xffffffffu, s1, 1);
        s1 += __shfl_xor_sync(0xffffffffu, s1, 2);
        l0r = l0r * a0 + s0;
        l1r = l1r * a1 + s1;
        m0r = mn0; m1r = mn1;

#pragma unroll
        for (int nb = 0; nb < 16; nb++) {
            Ofr[nb][0] *= a0; Ofr[nb][1] *= a0;
            Ofr[nb][2] *= a1; Ofr[nb][3] *= a1;
        }

        uint32_t Pa[4][4];
#pragma unroll
        for (int kc = 0; kc < 4; kc++) {
            Pa[kc][0] = packh2(S[2 * kc][0],     S[2 * kc][1]);
            Pa[kc][1] = packh2(S[2 * kc][2],     S[2 * kc][3]);
            Pa[kc][2] = packh2(S[2 * kc + 1][0], S[2 * kc + 1][1]);
            Pa[kc][3] = packh2(S[2 * kc + 1][2], S[2 * kc + 1][3]);
        }

#pragma unroll
        for (int kc = 0; kc < 4; kc++)
#pragma unroll
            for (int nbp = 0; nbp < 8; nbp++) {
                uint32_t bb[4];
                ldsm4t(bb, smem_to_u32(Vs + (kc * 16 + arow) * KP + nbp * 16 + acol));
                mma16816(Ofr[2 * nbp],     Pa[kc], bb);
                mma16816(Ofr[2 * nbp + 1], Pa[kc], bb + 2);
            }
    }

    // Epilogue: normalize, write fp16 y.
    const float i0 = 1.f / l0r, i1 = 1.f / l1r;
#pragma unroll
    for (int nb = 0; nb < 16; nb++) {
        size_t base0 = ((size_t)(b * TT + q0 + wrow + r0)) * DD + h * DK + nb * 8 + c0;
        size_t base1 = base0 + (size_t)8 * DD;
        *(__half2*)(yh + base0) = __floats2half2_rn(Ofr[nb][0] * i0, Ofr[nb][1] * i0);
        *(__half2*)(yh + base1) = __floats2half2_rn(Ofr[nb][2] * i1, Ofr[nb][3] * i1);
    }
}

// ---------------------------------------------------------------------------
// Launch
// ---------------------------------------------------------------------------
extern "C" void kernel_launch(void* const* d_in, const int* in_sizes, int n_in,
                              void* d_out, int out_size) {
    const float* x  = (const float*)d_in[0];
    const float* Wq = (const float*)d_in[1];
    const float* Wk = (const float*)d_in[2];
    const float* Wv = (const float*)d_in[3];
    const float* Wo = (const float*)d_in[4];
    float* out = (float*)d_out;

    __half *qh, *kh, *vh, *xh, *yh, *wt, *wo;
    cudaGetSymbolAddress((void**)&qh, g_qh);
    cudaGetSymbolAddress((void**)&kh, g_kh);
    cudaGetSymbolAddress((void**)&vh, g_vh);
    cudaGetSymbolAddress((void**)&xh, g_xh);
    cudaGetSymbolAddress((void**)&yh, g_yh);
    cudaGetSymbolAddress((void**)&wt, g_wt);
    cudaGetSymbolAddress((void**)&wo, g_wo);

    const int M = BB * TT;            // 4096

    // Single vectorized prep launch
    prep_all<<<(int)((N_ALL8 + 255) / 256), 256>>>(x, Wq, Wk, Wv, Wo, xh, wt, wo);

    cudaFuncSetAttribute(gemm_mma<true>,  cudaFuncAttributeMaxDynamicSharedMemorySize, GEMM_SMEM);
    cudaFuncSetAttribute(gemm_mma<false>, cudaFuncAttributeMaxDynamicSharedMemorySize, GEMM_SMEM);

    // Fused QKV projection + RoPE epilogue (q scaled by rs*log2e)
    gemm_mma<true><<<dim3(3072 / GBN, M / GBM), 256, GEMM_SMEM>>>(
        xh, wt, nullptr, qh, kh, vh, M, 3072, DD);

    // Attention (3-stage ring, 1 sync/tile, 2 CTAs/SM, exp2 softmax)
    cudaFuncSetAttribute(attn_h, cudaFuncAttributeMaxDynamicSharedMemorySize, ATT_SMEM);
    attn_h<<<dim3(TT / 64, HH, BB), 128, ATT_SMEM>>>(qh, kh, vh, yh);

    // Output projection (fp32 out)
    gemm_mma<false><<<dim3(DD / GBN, M / GBM), 256, GEMM_SMEM>>>(
        yh, wo, out, nullptr, nullptr, nullptr, M, DD, DD);
}